// round 2
// baseline (speedup 1.0000x reference)
#include <cuda_runtime.h>
#include <cstdint>
#include <cstddef>

#define HID 128
#define C3  384
#define TT  512
#define BB  4096
#define INP 28

// 3.2 GB scratch for precomputed input projections gx[t][b][384],
// split in two halves (each < 2 GB) : lo holds t in [0,256), hi t in [256,512).
__device__ __align__(16) float g_gx_lo[(size_t)256 * BB * C3];
__device__ __align__(16) float g_gx_hi[(size_t)256 * BB * C3];

// Packed dual-fp32 FMA (Blackwell f32x2: 2x the 3-reg FFMA issue rate).
static __device__ __forceinline__ float2 ffma2(float2 a, float2 b, float2 c) {
    unsigned long long ua, ub, uc, ud;
    ua = *reinterpret_cast<unsigned long long*>(&a);
    ub = *reinterpret_cast<unsigned long long*>(&b);
    uc = *reinterpret_cast<unsigned long long*>(&c);
    asm("fma.rn.f32x2 %0, %1, %2, %3;" : "=l"(ud) : "l"(ua), "l"(ub), "l"(uc));
    return *reinterpret_cast<float2*>(&ud);
}

static __device__ __forceinline__ float sig1(float x) {
    float e = __expf(-x);
    return __fdividef(1.0f, 1.0f + e);
}
static __device__ __forceinline__ float tanh1(float x) {
    float e = __expf(2.0f * x);            // inf for large x -> result 1
    return 1.0f - __fdividef(2.0f, e + 1.0f);
}

// ---------------------------------------------------------------------------
// Kernel A: gx[t][b][c] = sum_k x[b][t][k] * w_x[c/128][k][c%128] + b_x[c]
// Block: one batch row b (blockIdx.x), 64 timesteps (blockIdx.y*64). 384 thr.
// Thread: 16 timesteps x 4 cols, f32x2-paired over cols.
// ---------------------------------------------------------------------------
__global__ void __launch_bounds__(384)
gx_kernel(const float* __restrict__ x,
          const float* __restrict__ w_x,
          const float* __restrict__ b_x) {
    extern __shared__ float sm[];
    float* sXt = sm;            // [28][64]  transposed x: sXt[k][tt]
    float* sWx = sm + 64 * INP; // [28][384] sWx[k][c]

    const int b   = blockIdx.x;
    const int t0  = blockIdx.y * 64;
    const int tid = threadIdx.x;

    const float* xg = x + ((size_t)b * TT + t0) * INP;   // 64*28 contiguous
    for (int idx = tid; idx < 64 * INP; idx += 384) {
        int tt = idx / INP, k = idx % INP;
        sXt[k * 64 + tt] = xg[idx];
    }
    for (int idx = tid; idx < INP * C3; idx += 384) {
        int k = idx / C3, c = idx % C3;
        sWx[idx] = w_x[(size_t)(c >> 7) * INP * HID + k * HID + (c & 127)];
    }
    __syncthreads();

    const int cg = tid % 96;   // cols 4cg .. 4cg+3
    const int rg = tid / 96;   // timesteps rg*16 .. rg*16+15

    float2 a[16][2];
#pragma unroll
    for (int r = 0; r < 16; ++r) {
        a[r][0] = make_float2(0.f, 0.f);
        a[r][1] = make_float2(0.f, 0.f);
    }

    const float* xp0 = sXt + rg * 16;
    const float* wp0 = sWx + 4 * cg;

#pragma unroll 4
    for (int k = 0; k < INP; ++k) {
        float4 wv = *(const float4*)(wp0 + k * C3);
        float2 w0 = make_float2(wv.x, wv.y);
        float2 w1 = make_float2(wv.z, wv.w);
        const float* xp = xp0 + k * 64;
        float4 xa = *(const float4*)(xp);
        float4 xb = *(const float4*)(xp + 4);
        float4 xc = *(const float4*)(xp + 8);
        float4 xd = *(const float4*)(xp + 12);
        float xs[16] = {xa.x, xa.y, xa.z, xa.w, xb.x, xb.y, xb.z, xb.w,
                        xc.x, xc.y, xc.z, xc.w, xd.x, xd.y, xd.z, xd.w};
#pragma unroll
        for (int r = 0; r < 16; ++r) {
            float2 xx = make_float2(xs[r], xs[r]);
            a[r][0] = ffma2(xx, w0, a[r][0]);
            a[r][1] = ffma2(xx, w1, a[r][1]);
        }
    }

    float2 bx0 = *(const float2*)(b_x + 4 * cg);
    float2 bx1 = *(const float2*)(b_x + 4 * cg + 2);
#pragma unroll
    for (int r = 0; r < 16; ++r) {
        int t = t0 + rg * 16 + r;
        float* base = (t < 256) ? g_gx_lo : g_gx_hi;
        float4 o = make_float4(a[r][0].x + bx0.x, a[r][0].y + bx0.y,
                               a[r][1].x + bx1.x, a[r][1].y + bx1.y);
        *(float4*)(base + ((size_t)(t & 255) * BB + b) * C3 + 4 * cg) = o;
    }
}

// ---------------------------------------------------------------------------
// Kernel B: GRU recurrence + FC epilogue.
// 128 blocks x 32 batch rows, 256 threads (8 warps).
// smem: w_h [128][384] (196.6KB) + h state [128 units][36] (18.4KB).
// Warp w owns rows 4w..4w+3; lane ug owns units 4ug..4ug+3 for all 3 gates.
// ---------------------------------------------------------------------------
__global__ void __launch_bounds__(256, 1)
gru_kernel(const float* __restrict__ w_h,
           const float* __restrict__ b_h,
           const float* __restrict__ fc_w,
           const float* __restrict__ fc_b,
           float* __restrict__ out) {
    extern __shared__ float sm[];
    float* sWh = sm;              // [128][384]: sWh[k*384 + g*128 + u]
    float* sH  = sm + HID * C3;   // [128 units][36]: sH[u*36 + row]

    const int tid = threadIdx.x;
    const int w   = tid >> 5;     // warp -> rows 4w..4w+3
    const int ug  = tid & 31;     // lane -> units 4ug..4ug+3
    const int row0 = blockIdx.x * 32;

    for (int idx = tid; idx < HID * C3; idx += 256) {
        int k = idx / C3, c = idx % C3;
        sWh[idx] = w_h[(size_t)(c >> 7) * HID * HID + k * HID + (c & 127)];
    }
    for (int idx = tid; idx < HID * 36; idx += 256) sH[idx] = 0.0f;

    // biases: bh[g][p] covers units 4ug+2p .. 4ug+2p+1
    float2 bh[3][2];
#pragma unroll
    for (int g = 0; g < 3; ++g) {
        bh[g][0] = *(const float2*)(b_h + g * HID + 4 * ug);
        bh[g][1] = *(const float2*)(b_h + g * HID + 4 * ug + 2);
    }

    float hold[4][4];   // [row][unit]
#pragma unroll
    for (int r = 0; r < 4; ++r)
#pragma unroll
        for (int j = 0; j < 4; ++j) hold[r][j] = 0.0f;

    __syncthreads();

    // prefetch gx for t=0: pg[g][r]
    float4 pg[3][4];
#pragma unroll
    for (int r = 0; r < 4; ++r) {
        const float* gb = g_gx_lo + ((size_t)0 * BB + row0 + 4 * w + r) * C3 + 4 * ug;
#pragma unroll
        for (int g = 0; g < 3; ++g)
            pg[g][r] = __ldg((const float4*)(gb + g * HID));
    }

    for (int t = 0; t < TT; ++t) {
        // init accumulators from prefetched gx + biases
        float2 acc[4][3][2];
        float4 gxn[4];
#pragma unroll
        for (int r = 0; r < 4; ++r) {
            acc[r][0][0] = make_float2(pg[0][r].x + bh[0][0].x, pg[0][r].y + bh[0][0].y);
            acc[r][0][1] = make_float2(pg[0][r].z + bh[0][1].x, pg[0][r].w + bh[0][1].y);
            acc[r][1][0] = make_float2(pg[1][r].x + bh[1][0].x, pg[1][r].y + bh[1][0].y);
            acc[r][1][1] = make_float2(pg[1][r].z + bh[1][1].x, pg[1][r].w + bh[1][1].y);
            acc[r][2][0] = bh[2][0];
            acc[r][2][1] = bh[2][1];
            gxn[r] = pg[2][r];
        }

        // prefetch gx for t+1 (lands during the k-loop)
        if (t + 1 < TT) {
            int t2 = t + 1;
            const float* base = (t2 < 256) ? g_gx_lo : g_gx_hi;
#pragma unroll
            for (int r = 0; r < 4; ++r) {
                const float* gb = base + ((size_t)(t2 & 255) * BB + row0 + 4 * w + r) * C3 + 4 * ug;
#pragma unroll
                for (int g = 0; g < 3; ++g)
                    pg[g][r] = __ldg((const float4*)(gb + g * HID));
            }
        }

        // matvec: acc[r][g] += h[k] * w_h[g][k][units]
#pragma unroll 4
        for (int k = 0; k < HID; ++k) {
            float4 hk = *(const float4*)(sH + k * 36 + 4 * w);
            const float* wr = sWh + k * C3 + 4 * ug;
            float4 w0 = *(const float4*)(wr);
            float4 w1 = *(const float4*)(wr + HID);
            float4 w2 = *(const float4*)(wr + 2 * HID);
            float2 w0a = make_float2(w0.x, w0.y), w0b = make_float2(w0.z, w0.w);
            float2 w1a = make_float2(w1.x, w1.y), w1b = make_float2(w1.z, w1.w);
            float2 w2a = make_float2(w2.x, w2.y), w2b = make_float2(w2.z, w2.w);
            float hs[4] = {hk.x, hk.y, hk.z, hk.w};
#pragma unroll
            for (int r = 0; r < 4; ++r) {
                float2 hh = make_float2(hs[r], hs[r]);
                acc[r][0][0] = ffma2(hh, w0a, acc[r][0][0]);
                acc[r][0][1] = ffma2(hh, w0b, acc[r][0][1]);
                acc[r][1][0] = ffma2(hh, w1a, acc[r][1][0]);
                acc[r][1][1] = ffma2(hh, w1b, acc[r][1][1]);
                acc[r][2][0] = ffma2(hh, w2a, acc[r][2][0]);
                acc[r][2][1] = ffma2(hh, w2b, acc[r][2][1]);
            }
        }

        // gates + h update (thread-local)
        float hn[4][4];
#pragma unroll
        for (int r = 0; r < 4; ++r) {
            float gxnv[4] = {gxn[r].x, gxn[r].y, gxn[r].z, gxn[r].w};
#pragma unroll
            for (int p = 0; p < 2; ++p) {
#pragma unroll
                for (int q = 0; q < 2; ++q) {
                    int j = 2 * p + q;
                    float ar = (q == 0) ? acc[r][0][p].x : acc[r][0][p].y;
                    float az = (q == 0) ? acc[r][1][p].x : acc[r][1][p].y;
                    float an = (q == 0) ? acc[r][2][p].x : acc[r][2][p].y;
                    float rg = sig1(ar);
                    float zg = sig1(az);
                    float ng = tanh1(gxnv[j] + rg * an);
                    float hv = ng + zg * (hold[r][j] - ng);
                    hn[r][j] = hv;
                }
            }
        }

        __syncthreads();   // all reads of h(t) complete
#pragma unroll
        for (int j = 0; j < 4; ++j) {
            float4 hv = make_float4(hn[0][j], hn[1][j], hn[2][j], hn[3][j]);
            *(float4*)(sH + (4 * ug + j) * 36 + 4 * w) = hv;
        }
#pragma unroll
        for (int r = 0; r < 4; ++r)
#pragma unroll
            for (int j = 0; j < 4; ++j) hold[r][j] = hn[r][j];
        __syncthreads();   // h(t+1) visible
    }

    // FC epilogue: out[row0+lr][col] = sum_u h[lr][u]*fc_w[u][col] + fc_b[col]
    for (int idx = tid; idx < HID * 10; idx += 256) sWh[idx] = fc_w[idx];
    __syncthreads();
    for (int idx = tid; idx < 32 * 10; idx += 256) {
        int lr = idx / 10, col = idx % 10;
        float s = fc_b[col];
#pragma unroll 8
        for (int u = 0; u < HID; ++u)
            s += sH[u * 36 + lr] * sWh[u * 10 + col];
        out[(size_t)(row0 + lr) * 10 + col] = s;
    }
}

extern "C" void kernel_launch(void* const* d_in, const int* in_sizes, int n_in,
                              void* d_out, int out_size) {
    const float* x    = (const float*)d_in[0];
    const float* w_x  = (const float*)d_in[1];
    const float* b_x  = (const float*)d_in[2];
    const float* w_h  = (const float*)d_in[3];
    const float* b_h  = (const float*)d_in[4];
    const float* fc_w = (const float*)d_in[5];
    const float* fc_b = (const float*)d_in[6];
    float* out = (float*)d_out;

    const int smemA = (64 * INP + INP * C3) * sizeof(float);        // 50176 B
    const int smemB = (HID * C3 + HID * 36) * sizeof(float);        // 215040 B
    cudaFuncSetAttribute(gx_kernel,  cudaFuncAttributeMaxDynamicSharedMemorySize, smemA);
    cudaFuncSetAttribute(gru_kernel, cudaFuncAttributeMaxDynamicSharedMemorySize, smemB);

    dim3 gA(BB, TT / 64);
    gx_kernel<<<gA, 384, smemA>>>(x, w_x, b_x);
    gru_kernel<<<128, 256, smemB>>>(w_h, b_h, fc_w, fc_b, out);
}